// round 7
// baseline (speedup 1.0000x reference)
#include <cuda_runtime.h>
#include <cuda_bf16.h>
#include <cstdint>

#define S_    512
#define B_    64
#define I_    512
#define H_    512
#define SB_   (S_ * B_)
#define JG_   (4 * H_)

// ---------------- device globals (no allocs allowed) ----------------
__device__ float         g_gx[(size_t)S_ * 4 * H_ * B_];   // [s][gate][j][b]
__device__ __nv_bfloat16 g_xhi[(size_t)SB_ * I_];
__device__ __nv_bfloat16 g_xlo[(size_t)SB_ * I_];
__device__ __nv_bfloat16 g_wthi[(size_t)JG_ * I_];         // Wt[jg][k] = W_g[k][j]
__device__ __nv_bfloat16 g_wtlo[(size_t)JG_ * I_];
__device__ __nv_bfloat16 g_uthi[(size_t)JG_ * I_];         // Ut[jg][k] = U_g[k][j]
__device__ __nv_bfloat16 g_utlo[(size_t)JG_ * I_];
__device__ __nv_bfloat16 g_hb_hi[2][B_ * H_];              // h bf16 hi, [b][k]
__device__ __nv_bfloat16 g_hb_lo[2][B_ * H_];              // h bf16 lo
__device__ unsigned      g_bar_count;
__device__ unsigned      g_bar_release;

// ---------------- helpers ----------------
__device__ __forceinline__ uint32_t smem_u32(const void* p) {
    uint32_t a;
    asm("{ .reg .u64 t; cvta.to.shared.u64 t, %1; cvt.u32.u64 %0, t; }" : "=r"(a) : "l"(p));
    return a;
}
__device__ __forceinline__ void cp16(uint32_t dst, const void* src) {
    asm volatile("cp.async.ca.shared.global [%0], [%1], 16;" :: "r"(dst), "l"(src));
}
#define CP_COMMIT() asm volatile("cp.async.commit_group;" ::: "memory")
#define CP_WAITN(n) asm volatile("cp.async.wait_group %0;" :: "n"(n) : "memory")

__device__ __forceinline__ void mma16816(float* d, const uint32_t* a, const uint32_t* b) {
    asm volatile(
        "mma.sync.aligned.m16n8k16.row.col.f32.bf16.bf16.f32 "
        "{%0,%1,%2,%3}, {%4,%5,%6,%7}, {%8,%9}, {%0,%1,%2,%3};"
        : "+f"(d[0]), "+f"(d[1]), "+f"(d[2]), "+f"(d[3])
        : "r"(a[0]), "r"(a[1]), "r"(a[2]), "r"(a[3]), "r"(b[0]), "r"(b[1]));
}

__device__ __forceinline__ void grid_barrier(unsigned& phase, unsigned expected) {
    __syncthreads();
    if (threadIdx.x == 0) {
        __threadfence();
        unsigned ticket = atomicAdd(&g_bar_count, 1u);
        if (ticket == expected - 1u) {
            g_bar_count = 0u;
            __threadfence();
            atomicAdd(&g_bar_release, 1u);
        } else {
            volatile unsigned* rel = &g_bar_release;
            while (*rel == phase) { }
        }
        __threadfence();
        phase += 1u;
    }
    __syncthreads();
}

// =====================================================================
// Kernel 1: prep — bf16 hi/lo of x, W^T, U^T; zero h0(bf16) + c0 output
// =====================================================================
__global__ void prep_kernel(const float* __restrict__ x,
                            const float* __restrict__ Wi, const float* __restrict__ Wf,
                            const float* __restrict__ Wo, const float* __restrict__ Wc,
                            const float* __restrict__ Ui, const float* __restrict__ Uf,
                            const float* __restrict__ Uo, const float* __restrict__ Uc,
                            float* __restrict__ out)
{
    const size_t stride = (size_t)gridDim.x * blockDim.x;
    const size_t t0 = (size_t)blockIdx.x * blockDim.x + threadIdx.x;
    for (size_t i = t0; i < (size_t)SB_ * I_; i += stride) {
        float v = x[i];
        __nv_bfloat16 hi = __float2bfloat16_rn(v);
        g_xhi[i] = hi;
        g_xlo[i] = __float2bfloat16_rn(v - __bfloat162float(hi));
    }
    const float* Wg[4] = {Wi, Wf, Wo, Wc};
    const float* Ug[4] = {Ui, Uf, Uo, Uc};
    for (size_t i = t0; i < (size_t)JG_ * I_; i += stride) {
        int jg = (int)(i >> 9), k = (int)(i & 511);
        int g = jg >> 9, j = jg & 511;
        {
            float v = Wg[g][(size_t)k * H_ + j];
            __nv_bfloat16 hi = __float2bfloat16_rn(v);
            g_wthi[i] = hi;
            g_wtlo[i] = __float2bfloat16_rn(v - __bfloat162float(hi));
        }
        {
            float v = Ug[g][(size_t)k * H_ + j];
            __nv_bfloat16 hi = __float2bfloat16_rn(v);
            g_uthi[i] = hi;
            g_utlo[i] = __float2bfloat16_rn(v - __bfloat162float(hi));
        }
    }
    float* c0out = out + (size_t)S_ * B_ * H_ + (size_t)B_ * H_;
    for (size_t i = t0; i < (size_t)H_ * B_; i += stride) {
        c0out[i] = 0.0f;
        g_hb_hi[0][i] = __float2bfloat16_rn(0.0f);
        g_hb_lo[0][i] = __float2bfloat16_rn(0.0f);
    }
}

// =====================================================================
// Kernel 2: mma.sync bf16 3-split GEMM, gx = x @ W + b   (proven R6)
// =====================================================================
#define PADK    40
#define AS_ELE  (128 * PADK)
#define BS_ELE  (64 * PADK)
#define SM_BS   (4 * AS_ELE * 2)
#define SM_BIAS (SM_BS + 4 * BS_ELE * 2)
#define SM_TOT  (SM_BIAS + 256)

__global__ void __launch_bounds__(256, 2) gemm_a_kernel(
    const float* __restrict__ bi, const float* __restrict__ bf,
    const float* __restrict__ bo, const float* __restrict__ bc)
{
    extern __shared__ __align__(16) char sm[];
    const uint32_t smb = smem_u32(sm);
    __nv_bfloat16* As = (__nv_bfloat16*)sm;
    __nv_bfloat16* Bs = (__nv_bfloat16*)(sm + SM_BS);
    float* bias_s = (float*)(sm + SM_BIAS);
    float* Ct = (float*)sm;

    const int tid  = threadIdx.x;
    const int lane = tid & 31, wid = tid >> 5;
    const int wm = wid & 3, wn = wid >> 2;
    const int g5 = lane >> 2, tig = lane & 3;

    const int n0 = (blockIdx.x & 31) * 64;
    const int m0 = (blockIdx.x >> 5) * 128;
    const int gblk = n0 >> 9, j0 = n0 & 511;

    if (tid < 64) {
        const float* bg4[4] = {bi, bf, bo, bc};
        bias_s[tid] = bg4[gblk][j0 + tid];
    }

    float acc[2][4][4];
    #pragma unroll
    for (int mf = 0; mf < 2; mf++)
        #pragma unroll
        for (int nf = 0; nf < 4; nf++)
            #pragma unroll
            for (int q = 0; q < 4; q++) acc[mf][nf][q] = 0.0f;

    auto loadAB = [&](int buf, int kc) {
        #pragma unroll
        for (int i = 0; i < 4; i++) {
            int idx = tid + i * 256;
            int sp = idx >> 9, rem = idx & 511, row = rem >> 2, kcol = rem & 3;
            const __nv_bfloat16* src =
                (sp ? g_xlo : g_xhi) + (size_t)(m0 + row) * I_ + kc + kcol * 8;
            uint32_t dst = smb + ((buf * 2 + sp) * AS_ELE + row * PADK + kcol * 8) * 2;
            cp16(dst, src);
        }
        #pragma unroll
        for (int i = 0; i < 2; i++) {
            int idx = tid + i * 256;
            int sp = idx >> 8, rem = idx & 255, row = rem >> 2, kcol = rem & 3;
            const __nv_bfloat16* src =
                (sp ? g_wtlo : g_wthi) + (size_t)(n0 + row) * I_ + kc + kcol * 8;
            uint32_t dst = smb + SM_BS + ((buf * 2 + sp) * BS_ELE + row * PADK + kcol * 8) * 2;
            cp16(dst, src);
        }
    };

    loadAB(0, 0);  CP_COMMIT();
    loadAB(1, 32); CP_COMMIT();

    for (int kc = 0; kc < 16; kc++) {
        if (kc == 15) CP_WAITN(0); else CP_WAITN(1);
        __syncthreads();
        const int buf = kc & 1;
        const __nv_bfloat16* Ah = As + (buf * 2 + 0) * AS_ELE;
        const __nv_bfloat16* Al = As + (buf * 2 + 1) * AS_ELE;
        const __nv_bfloat16* Bh = Bs + (buf * 2 + 0) * BS_ELE;
        const __nv_bfloat16* Bl = Bs + (buf * 2 + 1) * BS_ELE;
        #pragma unroll
        for (int k16 = 0; k16 < 2; k16++) {
            const int ko = k16 * 16 + 2 * tig;
            uint32_t ah[2][4], al[2][4], bh[4][2], bl[4][2];
            #pragma unroll
            for (int mf = 0; mf < 2; mf++) {
                int r0 = wm * 32 + mf * 16 + g5;
                ah[mf][0] = *(const uint32_t*)(Ah + r0 * PADK + ko);
                ah[mf][1] = *(const uint32_t*)(Ah + (r0 + 8) * PADK + ko);
                ah[mf][2] = *(const uint32_t*)(Ah + r0 * PADK + ko + 8);
                ah[mf][3] = *(const uint32_t*)(Ah + (r0 + 8) * PADK + ko + 8);
                al[mf][0] = *(const uint32_t*)(Al + r0 * PADK + ko);
                al[mf][1] = *(const uint32_t*)(Al + (r0 + 8) * PADK + ko);
                al[mf][2] = *(const uint32_t*)(Al + r0 * PADK + ko + 8);
                al[mf][3] = *(const uint32_t*)(Al + (r0 + 8) * PADK + ko + 8);
            }
            #pragma unroll
            for (int nf = 0; nf < 4; nf++) {
                int n = wn * 32 + nf * 8 + g5;
                bh[nf][0] = *(const uint32_t*)(Bh + n * PADK + ko);
                bh[nf][1] = *(const uint32_t*)(Bh + n * PADK + ko + 8);
                bl[nf][0] = *(const uint32_t*)(Bl + n * PADK + ko);
                bl[nf][1] = *(const uint32_t*)(Bl + n * PADK + ko + 8);
            }
            #pragma unroll
            for (int mf = 0; mf < 2; mf++)
                #pragma unroll
                for (int nf = 0; nf < 4; nf++) {
                    mma16816(acc[mf][nf], ah[mf], bh[nf]);
                    mma16816(acc[mf][nf], al[mf], bh[nf]);
                    mma16816(acc[mf][nf], ah[mf], bl[nf]);
                }
        }
        __syncthreads();
        if (kc < 14) { loadAB(buf, (kc + 2) * 32); CP_COMMIT(); }
    }

    #pragma unroll
    for (int mf = 0; mf < 2; mf++)
        #pragma unroll
        for (int nf = 0; nf < 4; nf++) {
            int r = wm * 32 + mf * 16 + g5;
            int c = wn * 32 + nf * 8 + 2 * tig;
            Ct[r * 65 + c]           = acc[mf][nf][0];
            Ct[r * 65 + c + 1]       = acc[mf][nf][1];
            Ct[(r + 8) * 65 + c]     = acc[mf][nf][2];
            Ct[(r + 8) * 65 + c + 1] = acc[mf][nf][3];
        }
    __syncthreads();
    {
        const int r = tid & 127, ch = tid >> 7;
        const int s = (m0 + r) >> 6, b = (m0 + r) & 63;
        float* dst = g_gx + (((size_t)s * 4 + gblk) * H_ + j0 + ch * 32) * B_ + b;
        #pragma unroll
        for (int c = 0; c < 32; c++)
            dst[(size_t)c * B_] = Ct[r * 65 + ch * 32 + c] + bias_s[ch * 32 + c];
    }
}

// =====================================================================
// Kernel 3: tensor-core recurrence. 64 blocks, each owns 8 j x 4 gates.
// Per step: h[64x512] @ Ut^T slice -> pre[64x32], bf16 3-split mma.
// =====================================================================
#define RS2    520                         // padded row stride (bf16 elems)
#define US_HI  0
#define US_LO  (32 * RS2 * 2)              // 33280
#define HS_HI  (2 * 32 * RS2 * 2)          // 66560
#define HS_LO  (HS_HI + 64 * RS2 * 2)      // 133120
#define SM2_TOT (HS_LO + 64 * RS2 * 2)     // 199680
#define REDP   34
#define NW2    64

__global__ void __launch_bounds__(256, 1) lstm_b2_kernel(float* __restrict__ out)
{
    extern __shared__ __align__(16) char sm[];
    const uint32_t smb = smem_u32(sm);
    __shared__ float s_c[8][B_];
    __shared__ float hswf[B_][8];
    __shared__ __nv_bfloat16 hswh[2][B_][8];

    const int tid  = threadIdx.x;
    const int bid  = blockIdx.x;
    const int lane = tid & 31, wid = tid >> 5;
    const int g5 = lane >> 2, tig = lane & 3;
    const int mg = wid & 1;            // m32 group
    const int kq = wid >> 1;           // k quarter (32k per chunk slice)
    const int j0 = bid * 8;

    unsigned phase = *(volatile unsigned*)&g_bar_release;

    ((float*)s_c)[tid] = 0.0f;
    ((float*)s_c)[tid + 256] = 0.0f;

    // ---- stage Ut slice (32 jg rows x 512 k, hi+lo) into smem ----
    for (int i = tid; i < 2 * 32 * 64; i += 256) {
        int sp = i >> 11, rem = i & 2047;
        int n = rem >> 6, seg = rem & 63;
        int g = n >> 3, j = j0 + (n & 7);
        const __nv_bfloat16* src = (sp ? g_utlo : g_uthi) + ((size_t)g * 512 + j) * 512 + seg * 8;
        uint32_t dst = smb + (sp ? US_LO : US_HI) + n * (RS2 * 2) + seg * 16;
        cp16(dst, src);
    }
    CP_COMMIT(); CP_WAITN(0);
    __syncthreads();

    const __nv_bfloat16* Ushi = (const __nv_bfloat16*)(sm + US_HI);
    const __nv_bfloat16* Uslo = (const __nv_bfloat16*)(sm + US_LO);
    const __nv_bfloat16* hshi = (const __nv_bfloat16*)(sm + HS_HI);
    const __nv_bfloat16* hslo = (const __nv_bfloat16*)(sm + HS_LO);
    float* red = (float*)(sm + HS_HI);     // alias: h staging dead after mma

    for (int s = 0; s < S_; s++) {
        const __nv_bfloat16* hb_hi = g_hb_hi[s & 1];
        const __nv_bfloat16* hb_lo = g_hb_lo[s & 1];

        // issue 4 chunked cp.async groups for h (hi+lo)
        #pragma unroll
        for (int c = 0; c < 4; c++) {
            #pragma unroll
            for (int i = 0; i < 8; i++) {
                int idx = tid + i * 256;
                int sp = idx >> 10, rem = idx & 1023;
                int b = rem >> 4, seg = rem & 15;
                const __nv_bfloat16* src = (sp ? hb_lo : hb_hi) + b * 512 + c * 128 + seg * 8;
                uint32_t dst = smb + (sp ? HS_LO : HS_HI) + b * (RS2 * 2) + c * 256 + seg * 16;
                cp16(dst, src);
            }
            CP_COMMIT();
        }

        // prefetch gx for epilogue (2 items/thread x 4 gates)
        float gxr[2][4];
        #pragma unroll
        for (int pp = 0; pp < 2; pp++) {
            int p = tid + pp * 256;
            int b = p & 63, jj = p >> 6;
            #pragma unroll
            for (int g = 0; g < 4; g++)
                gxr[pp][g] = g_gx[(((size_t)s * 4 + g) * H_ + j0 + jj) * B_ + b];
        }

        float acc[2][4][4];
        #pragma unroll
        for (int mt = 0; mt < 2; mt++)
            #pragma unroll
            for (int nt = 0; nt < 4; nt++)
                #pragma unroll
                for (int q = 0; q < 4; q++) acc[mt][nt][q] = 0.0f;

        #pragma unroll
        for (int c = 0; c < 4; c++) {
            if (c == 0)      CP_WAITN(3);
            else if (c == 1) CP_WAITN(2);
            else if (c == 2) CP_WAITN(1);
            else             CP_WAITN(0);
            __syncthreads();
            #pragma unroll
            for (int s16 = 0; s16 < 2; s16++) {
                const int k0 = c * 128 + kq * 32 + s16 * 16;
                const int ko = k0 + 2 * tig;
                uint32_t ah[2][4], al[2][4], bh[4][2], bl[4][2];
                #pragma unroll
                for (int mt = 0; mt < 2; mt++) {
                    int r = mg * 32 + mt * 16 + g5;
                    ah[mt][0] = *(const uint32_t*)(hshi + r * RS2 + ko);
                    ah[mt][1] = *(const uint32_t*)(hshi + (r + 8) * RS2 + ko);
                    ah[mt][2] = *(const uint32_t*)(hshi + r * RS2 + ko + 8);
                    ah[mt][3] = *(const uint32_t*)(hshi + (r + 8) * RS2 + ko + 8);
                    al[mt][0] = *(const uint32_t*)(hslo + r * RS2 + ko);
                    al[mt][1] = *(const uint32_t*)(hslo + (r + 8) * RS2 + ko);
                    al[mt][2] = *(const uint32_t*)(hslo + r * RS2 + ko + 8);
                    al[mt][3] = *(const uint32_t*)(hslo + (r + 8) * RS2 + ko + 8);
                }
                #pragma unroll
                for (int nt = 0; nt < 4; nt++) {
                    int n = nt * 8 + g5;
                    bh[nt][0] = *(const uint32_t*)(Ushi + n * RS2 + ko);
                    bh[nt][1] = *(const uint32_t*)(Ushi + n * RS2 + ko + 8);
                    bl[nt][0] = *(const uint32_t*)(Uslo + n * RS2 + ko);
                    bl[nt][1] = *(const uint32_t*)(Uslo + n * RS2 + ko + 8);
                }
                #pragma unroll
                for (int mt = 0; mt < 2; mt++)
                    #pragma unroll
                    for (int nt = 0; nt < 4; nt++) {
                        mma16816(acc[mt][nt], ah[mt], bh[nt]);
                        mma16816(acc[mt][nt], al[mt], bh[nt]);
                        mma16816(acc[mt][nt], ah[mt], bl[nt]);
                    }
            }
        }
        __syncthreads();            // all mma reads of hS done -> red may alias
        #pragma unroll
        for (int mt = 0; mt < 2; mt++)
            #pragma unroll
            for (int nt = 0; nt < 4; nt++) {
                float* rp = red + ((size_t)kq * 64 + mg * 32 + mt * 16 + g5) * REDP
                              + nt * 8 + 2 * tig;
                rp[0] = acc[mt][nt][0];
                rp[1] = acc[mt][nt][1];
                rp[8 * REDP]     = acc[mt][nt][2];
                rp[8 * REDP + 1] = acc[mt][nt][3];
            }
        __syncthreads();

        // ---- epilogue: reduce k-quarters, activations, h update ----
        #pragma unroll
        for (int pp = 0; pp < 2; pp++) {
            int p = tid + pp * 256;
            int b = p & 63, jj = p >> 6;
            float pre[4];
            #pragma unroll
            for (int g = 0; g < 4; g++) {
                float v = gxr[pp][g];
                int n = g * 8 + jj;
                #pragma unroll
                for (int q = 0; q < 4; q++)
                    v += red[((size_t)q * 64 + b) * REDP + n];
                pre[g] = v;
            }
            float it = 1.0f / (1.0f + __expf(-pre[0]));
            float ft = 1.0f / (1.0f + __expf(-pre[1]));
            float ot = 1.0f / (1.0f + __expf(-pre[2]));
            float ct = tanhf(pre[3]);
            float cn = ft * s_c[jj][b] + it * ct;
            s_c[jj][b] = cn;
            float hn = ot * tanhf(cn);
            hswf[b][jj] = hn;
            __nv_bfloat16 hi = __float2bfloat16_rn(hn);
            hswh[0][b][jj] = hi;
            hswh[1][b][jj] = __float2bfloat16_rn(hn - __bfloat162float(hi));
        }
        __syncthreads();

        if (tid < 128) {    // hs[s][b][j0..j0+7] as 2 float4 per row
            int b = tid >> 1, hf = tid & 1;
            float4 hv = *(const float4*)&hswf[b][hf * 4];
            *(float4*)(out + ((size_t)s * B_ + b) * H_ + j0 + hf * 4) = hv;
            if (s == S_ - 1)
                *(float4*)(out + (size_t)S_ * B_ * H_ + (size_t)b * H_ + j0 + hf * 4) = hv;
        }
        if (tid < 64) {     // h bf16 hi: 8 elems = 16B per row
            *(uint4*)(g_hb_hi[(s + 1) & 1] + (size_t)tid * H_ + j0) = *(const uint4*)&hswh[0][tid][0];
        } else if (tid < 128) {
            int b = tid - 64;
            *(uint4*)(g_hb_lo[(s + 1) & 1] + (size_t)b * H_ + j0) = *(const uint4*)&hswh[1][b][0];
        }

        if (s < S_ - 1) grid_barrier(phase, NW2);
    }
}

// =====================================================================
extern "C" void kernel_launch(void* const* d_in, const int* in_sizes, int n_in,
                              void* d_out, int out_size) {
    (void)in_sizes; (void)n_in; (void)out_size;
    const float* x  = (const float*)d_in[0];
    const float* Wi = (const float*)d_in[1], *Wf = (const float*)d_in[2];
    const float* Wo = (const float*)d_in[3], *Wc = (const float*)d_in[4];
    const float* Ui = (const float*)d_in[5], *Uf = (const float*)d_in[6];
    const float* Uo = (const float*)d_in[7], *Uc = (const float*)d_in[8];
    const float* bi = (const float*)d_in[9], *bf = (const float*)d_in[10];
    const float* bo = (const float*)d_in[11], *bc = (const float*)d_in[12];
    float* out = (float*)d_out;

    cudaFuncSetAttribute(gemm_a_kernel, cudaFuncAttributeMaxDynamicSharedMemorySize, SM_TOT);
    cudaFuncSetAttribute(lstm_b2_kernel, cudaFuncAttributeMaxDynamicSharedMemorySize, SM2_TOT);

    prep_kernel<<<2048, 256>>>(x, Wi, Wf, Wo, Wc, Ui, Uf, Uo, Uc, out);
    gemm_a_kernel<<<8192, 256, SM_TOT>>>(bi, bf, bo, bc);
    lstm_b2_kernel<<<NW2, 256, SM2_TOT>>>(out);
}